// round 1
// baseline (speedup 1.0000x reference)
#include <cuda_runtime.h>
#include <cuda_bf16.h>

#define D   128
#define HS  128
#define MAXV 1000064
#define MAXG 16384
#define AP  136   // padded smem row length (bf16 elems): 128 + 8

// ---------------- device scratch (no allocations allowed) ----------------
__device__ float g_e[MAXV];
__device__ float g_aexp[MAXV];
__device__ int   g_starts[MAXG + 1];
__device__ float g_ginv[MAXG];
__device__ __align__(16) __nv_bfloat16 g_Whi[HS * D];
__device__ __align__(16) __nv_bfloat16 g_Wlo[HS * D];

// ---------------- helpers ----------------
__device__ __forceinline__ unsigned su32(const void* p) {
    return (unsigned)__cvta_generic_to_shared(p);
}
__device__ __forceinline__ unsigned pk(__nv_bfloat16 a, __nv_bfloat16 b) {
    unsigned short ua = *(unsigned short*)&a, ub = *(unsigned short*)&b;
    return (unsigned)ua | ((unsigned)ub << 16);
}
__device__ __forceinline__ float tanh_fast(float x) {
    // tanh(x) = 1 - 2/(exp(2x)+1); exact limits at +/-inf, err ~1e-6
    float e2 = __expf(2.0f * x);
    return 1.0f - __fdividef(2.0f, e2 + 1.0f);
}

#define LDSM4(r0, r1, r2, r3, addr)                                          \
    asm volatile("ldmatrix.sync.aligned.m8n8.x4.shared.b16 {%0,%1,%2,%3}, [%4];" \
                 : "=r"(r0), "=r"(r1), "=r"(r2), "=r"(r3) : "r"(addr))

#define MMA16816(c, a0, a1, a2, a3, b0, b1)                                  \
    asm volatile(                                                            \
        "mma.sync.aligned.m16n8k16.row.col.f32.bf16.bf16.f32 "               \
        "{%0,%1,%2,%3},{%4,%5,%6,%7},{%8,%9},{%0,%1,%2,%3};"                 \
        : "+f"(c[0]), "+f"(c[1]), "+f"(c[2]), "+f"(c[3])                     \
        : "r"(a0), "r"(a1), "r"(a2), "r"(a3), "r"(b0), "r"(b1))

// ---------------- K_w: split W into bf16 hi/lo ----------------
__global__ void k_prep_w(const float* __restrict__ W) {
    int i = blockIdx.x * 256 + threadIdx.x;
    if (i < HS * D) {
        float x = W[i];
        __nv_bfloat16 h = __float2bfloat16(x);
        g_Whi[i] = h;
        g_Wlo[i] = __float2bfloat16(x - __bfloat162float(h));
    }
}

// ---------------- K0: segment boundaries from sorted batch ----------------
// starts[g] = first index i with batch[i] >= g ; starts[G] = V
__global__ void k_bounds(const void* __restrict__ batch_raw, int V, int G) {
    int i = blockIdx.x * 256 + threadIdx.x;
    if (i >= V) return;
    // runtime dtype detection: if data is int32, reading a u64 mid-array
    // combines two nonzero sorted values -> huge number.
    bool is64 =
        (((const unsigned long long*)batch_raw)[V / 2 - 1] < (1ULL << 31));
    auto bat = [&](int j) -> int {
        return is64 ? (int)((const long long*)batch_raw)[j]
                    : ((const int*)batch_raw)[j];
    };
    int cur = bat(i);
    int prev = (i == 0) ? -1 : bat(i - 1);
    for (int g = prev + 1; g <= cur && g <= G; ++g) g_starts[g] = i;
    if (i == V - 1)
        for (int g = cur + 1; g <= G; ++g) g_starts[g] = V;
}

// ---------------- K1: e = tanh(H W^T + b) . w_score  (split-bf16 MMA) -----
// CTA: 128 rows x 128 cols, 256 threads = 8 warps as 4(M)x2(N),
// warp tile 32x64. 3 passes: Ahi*Bhi + Ahi*Blo + Alo*Bhi.
__global__ __launch_bounds__(256) void k1_gemm_e(
    const float* __restrict__ H, const float* __restrict__ bp,
    const float* __restrict__ ws, int V) {
    extern __shared__ __align__(16) char smem_raw[];
    __nv_bfloat16* sAhi = (__nv_bfloat16*)smem_raw;
    __nv_bfloat16* sAlo = sAhi + 128 * AP;
    __nv_bfloat16* sBhi = sAlo + 128 * AP;
    __nv_bfloat16* sBlo = sBhi + 128 * AP;
    float* se = (float*)(sBlo + 128 * AP);
    float* sb = se + 128;
    float* sw = sb + 128;

    int tid = threadIdx.x;

    if (tid < 128) {
        sb[tid] = bp[tid];
        sw[tid] = ws[tid];
        se[tid] = 0.0f;
    }

    // stage W (pre-split bf16) into padded smem
#pragma unroll
    for (int i = tid; i < (HS * D) / 4; i += 256) {
        uint2 vh = ((const uint2*)g_Whi)[i];
        uint2 vl = ((const uint2*)g_Wlo)[i];
        int row = i >> 5, col = (i & 31) << 2;
        *(uint2*)(sBhi + row * AP + col) = vh;
        *(uint2*)(sBlo + row * AP + col) = vl;
    }

    // stage H tile: split fp32 -> bf16 hi/lo
    {
        int row = tid >> 1;
        int ch = (tid & 1) * 64;
        long grow = (long)blockIdx.x * 128 + row;
        const float4* src =
            (const float4*)(H + (size_t)grow * D + ch);
#pragma unroll
        for (int j = 0; j < 16; ++j) {
            float4 v;
            if (grow < (long)V) v = src[j];
            else v = make_float4(0.f, 0.f, 0.f, 0.f);
            __nv_bfloat16 h0 = __float2bfloat16(v.x);
            __nv_bfloat16 h1 = __float2bfloat16(v.y);
            __nv_bfloat16 h2 = __float2bfloat16(v.z);
            __nv_bfloat16 h3 = __float2bfloat16(v.w);
            __nv_bfloat16 l0 = __float2bfloat16(v.x - __bfloat162float(h0));
            __nv_bfloat16 l1 = __float2bfloat16(v.y - __bfloat162float(h1));
            __nv_bfloat16 l2 = __float2bfloat16(v.z - __bfloat162float(h2));
            __nv_bfloat16 l3 = __float2bfloat16(v.w - __bfloat162float(h3));
            int col = ch + j * 4;
            uint2 ph; ph.x = pk(h0, h1); ph.y = pk(h2, h3);
            uint2 pl; pl.x = pk(l0, l1); pl.y = pk(l2, l3);
            *(uint2*)(sAhi + row * AP + col) = ph;
            *(uint2*)(sAlo + row * AP + col) = pl;
        }
    }
    __syncthreads();

    int lane = tid & 31, wid = tid >> 5;
    int wm = wid >> 1, wn = wid & 1;
    int rb = wm * 32, cb = wn * 64;

    float acc[2][8][4];
#pragma unroll
    for (int a = 0; a < 2; a++)
#pragma unroll
        for (int b = 0; b < 8; b++)
#pragma unroll
            for (int c = 0; c < 4; c++) acc[a][b][c] = 0.f;

    // lane-derived smem byte offsets for ldmatrix
    unsigned aoff = ((rb + (lane & 15)) * AP + ((lane >> 4) << 3)) * 2;
    unsigned boff =
        ((cb + (lane & 7) + ((lane >> 4) << 3)) * AP + (((lane >> 3) & 1) << 3)) * 2;

#pragma unroll
    for (int pass = 0; pass < 3; ++pass) {
        unsigned abase = su32(pass == 2 ? sAlo : sAhi) + aoff;
        unsigned bbase = su32(pass == 1 ? sBlo : sBhi) + boff;
#pragma unroll
        for (int kk = 0; kk < 8; ++kk) {
            unsigned a0, a1, a2, a3, a4, a5, a6, a7;
            LDSM4(a0, a1, a2, a3, abase + kk * 32);
            LDSM4(a4, a5, a6, a7, abase + kk * 32 + 16 * AP * 2);
            unsigned bf[16];
#pragma unroll
            for (int p = 0; p < 4; ++p)
                LDSM4(bf[4 * p], bf[4 * p + 1], bf[4 * p + 2], bf[4 * p + 3],
                      bbase + kk * 32 + p * (16 * AP * 2));
#pragma unroll
            for (int nt = 0; nt < 8; ++nt) {
                int bi = (nt >> 1) * 4 + ((nt & 1) << 1);
                MMA16816(acc[0][nt], a0, a1, a2, a3, bf[bi], bf[bi + 1]);
                MMA16816(acc[1][nt], a4, a5, a6, a7, bf[bi], bf[bi + 1]);
            }
        }
    }

    // epilogue: e_row += tanh(acc + b[col]) * ws[col], reduce over cols
    float bv[16], wv[16];
#pragma unroll
    for (int nt = 0; nt < 8; ++nt)
#pragma unroll
        for (int par = 0; par < 2; ++par) {
            int col = cb + nt * 8 + (lane & 3) * 2 + par;
            bv[nt * 2 + par] = sb[col];
            wv[nt * 2 + par] = sw[col];
        }
    float ps[4] = {0.f, 0.f, 0.f, 0.f};
#pragma unroll
    for (int mi = 0; mi < 2; ++mi)
#pragma unroll
        for (int nt = 0; nt < 8; ++nt)
#pragma unroll
            for (int e = 0; e < 4; ++e) {
                float z = acc[mi][nt][e] + bv[nt * 2 + (e & 1)];
                float t = tanh_fast(z);
                ps[mi * 2 + (e >> 1)] += t * wv[nt * 2 + (e & 1)];
            }
#pragma unroll
    for (int q = 0; q < 4; ++q) {
        ps[q] += __shfl_xor_sync(0xffffffffu, ps[q], 1);
        ps[q] += __shfl_xor_sync(0xffffffffu, ps[q], 2);
    }
    if ((lane & 3) == 0) {
#pragma unroll
        for (int q = 0; q < 4; ++q) {
            int r = rb + (q >> 1) * 16 + (lane >> 2) + (q & 1) * 8;
            atomicAdd(&se[r], ps[q]);
        }
    }
    __syncthreads();
    if (tid < 128) {
        long grow = (long)blockIdx.x * 128 + tid;
        if (grow < (long)V) g_e[grow] = se[tid];
    }
}

// ---------------- K2: per-segment max / exp / sum ----------------
__global__ void k2_softmax_stats() {
    __shared__ float red[128];
    int g = blockIdx.x, tid = threadIdx.x;
    int s = g_starts[g], t = g_starts[g + 1];

    float m = -1e30f;
    for (int i = s + tid; i < t; i += 128) m = fmaxf(m, g_e[i]);
    red[tid] = m;
    __syncthreads();
#pragma unroll
    for (int o = 64; o > 0; o >>= 1) {
        if (tid < o) red[tid] = fmaxf(red[tid], red[tid + o]);
        __syncthreads();
    }
    m = red[0];
    __syncthreads();

    float sum = 0.f;
    for (int i = s + tid; i < t; i += 128) {
        float a = __expf(g_e[i] - m);
        g_aexp[i] = a;
        sum += a;
    }
    red[tid] = sum;
    __syncthreads();
#pragma unroll
    for (int o = 64; o > 0; o >>= 1) {
        if (tid < o) red[tid] += red[tid + o];
        __syncthreads();
    }
    if (tid == 0) g_ginv[g] = 1.0f / fmaxf(red[0], 1e-12f);
}

// ---------------- K3: pooled output ----------------
__global__ void k3_pool(const float* __restrict__ H, float* __restrict__ out) {
    int g = blockIdx.x, d = threadIdx.x;
    int s = g_starts[g], t = g_starts[g + 1];
    float a0 = 0.f, a1 = 0.f, a2 = 0.f, a3 = 0.f;
    int i = s;
    for (; i + 3 < t; i += 4) {
        a0 += g_aexp[i]     * H[(size_t)(i)     * D + d];
        a1 += g_aexp[i + 1] * H[(size_t)(i + 1) * D + d];
        a2 += g_aexp[i + 2] * H[(size_t)(i + 2) * D + d];
        a3 += g_aexp[i + 3] * H[(size_t)(i + 3) * D + d];
    }
    for (; i < t; ++i) a0 += g_aexp[i] * H[(size_t)i * D + d];
    out[(size_t)g * D + d] = (a0 + a1 + a2 + a3) * g_ginv[g];
}

// ---------------- launch ----------------
extern "C" void kernel_launch(void* const* d_in, const int* in_sizes, int n_in,
                              void* d_out, int out_size) {
    const float* H  = (const float*)d_in[0];
    const void*  bt = d_in[1];
    const float* Wp = (const float*)d_in[2];
    const float* bp = (const float*)d_in[3];
    const float* ws = (const float*)d_in[4];
    float* out = (float*)d_out;

    int V = in_sizes[1];
    int G = out_size / D;
    if (G > MAXG) G = MAXG;

    static const int SMEM1 = (4 * 128 * AP) * 2 + 3 * 128 * 4;  // 140800
    cudaFuncSetAttribute(k1_gemm_e, cudaFuncAttributeMaxDynamicSharedMemorySize,
                         SMEM1);

    k_prep_w<<<(HS * D + 255) / 256, 256>>>(Wp);
    k_bounds<<<(V + 255) / 256, 256>>>(bt, V, G);
    k1_gemm_e<<<(V + 127) / 128, 256, SMEM1>>>(H, bp, ws, V);
    k2_softmax_stats<<<G, 128>>>();
    k3_pool<<<G, 128>>>(H, out);
}

// round 3
// speedup vs baseline: 1.2254x; 1.2254x over previous
#include <cuda_runtime.h>
#include <cuda_bf16.h>
#include <cstdint>

#define D    128
#define HS   128
#define MAXV 1000064
#define MAXG 16384
#define AP   136      // padded smem row pitch in bf16 elems
#define TILE 64       // rows per tile
#define NSM  148

// ---------------- device scratch ----------------
__device__ float g_e[MAXV];
__device__ int   g_starts[MAXG + 1];
__device__ __align__(16) __nv_bfloat16 g_Whi[HS * D];
__device__ __align__(16) __nv_bfloat16 g_Wlo[HS * D];

// ---------------- smem layout (bytes) ----------------
#define SM_SB    0                      // 128 f32 bias
#define SM_SW    512                    // 128 f32 w_score
#define SM_BHI   1024                   // 128 x AP bf16 = 34816
#define SM_BLO   (SM_BHI + 34816)       // 35840
#define SM_A0HI  (SM_BLO + 34816)       // 70656   (64 x AP bf16 = 17408 each)
#define SM_A0LO  (SM_A0HI + 17408)
#define SM_A1HI  (SM_A0LO + 17408)
#define SM_A1LO  (SM_A1HI + 17408)
#define SM_SE    (SM_A1LO + 17408)      // 2 x 64 f32 = 512
#define SMEM1_TOTAL (SM_SE + 512)       // 140800

// ---------------- helpers ----------------
__device__ __forceinline__ unsigned su32(const void* p) {
    return (unsigned)__cvta_generic_to_shared(p);
}
__device__ __forceinline__ unsigned pk(__nv_bfloat16 a, __nv_bfloat16 b) {
    unsigned short ua = *(unsigned short*)&a, ub = *(unsigned short*)&b;
    return (unsigned)ua | ((unsigned)ub << 16);
}
__device__ __forceinline__ float tanh_fast(float x) {
    float e2 = __expf(2.0f * x);
    return 1.0f - __fdividef(2.0f, e2 + 1.0f);
}

#define LDSM4(r0, r1, r2, r3, addr)                                          \
    asm volatile("ldmatrix.sync.aligned.m8n8.x4.shared.b16 {%0,%1,%2,%3}, [%4];" \
                 : "=r"(r0), "=r"(r1), "=r"(r2), "=r"(r3) : "r"(addr))

#define MMA16816(c, a0, a1, a2, a3, b0, b1)                                  \
    asm volatile(                                                            \
        "mma.sync.aligned.m16n8k16.row.col.f32.bf16.bf16.f32 "               \
        "{%0,%1,%2,%3},{%4,%5,%6,%7},{%8,%9},{%0,%1,%2,%3};"                 \
        : "+f"(c[0]), "+f"(c[1]), "+f"(c[2]), "+f"(c[3])                     \
        : "r"(a0), "r"(a1), "r"(a2), "r"(a3), "r"(b0), "r"(b1))

// ---------------- small kernels ----------------
__global__ void k_prep_w(const float* __restrict__ W) {
    int i = blockIdx.x * 256 + threadIdx.x;
    if (i < HS * D) {
        float x = W[i];
        __nv_bfloat16 h = __float2bfloat16(x);
        g_Whi[i] = h;
        g_Wlo[i] = __float2bfloat16(x - __bfloat162float(h));
    }
}

__global__ void k_bounds(const void* __restrict__ batch_raw, int V, int G) {
    int i = blockIdx.x * 256 + threadIdx.x;
    if (i >= V) return;
    bool is64 =
        (((const unsigned long long*)batch_raw)[V / 2 - 1] < (1ULL << 31));
    auto bat = [&](int j) -> int {
        return is64 ? (int)((const long long*)batch_raw)[j]
                    : ((const int*)batch_raw)[j];
    };
    int cur = bat(i);
    int prev = (i == 0) ? -1 : bat(i - 1);
    for (int g = prev + 1; g <= cur && g <= G; ++g) g_starts[g] = i;
    if (i == V - 1)
        for (int g = cur + 1; g <= G; ++g) g_starts[g] = V;
}

// ---------------- K1: persistent split-bf16 HMMA + tanh-dot epilogue ------
// stage one TILE x 128 fp32 tile -> bf16 hi/lo (padded row-major)
__device__ __forceinline__ void stage_tile(char* smem, const float* __restrict__ H,
                                           long tile, int buf, int V,
                                           int tpart, int npart) {
    __nv_bfloat16* dhi = (__nv_bfloat16*)(smem + (buf ? SM_A1HI : SM_A0HI));
    __nv_bfloat16* dlo = (__nv_bfloat16*)(smem + (buf ? SM_A1LO : SM_A0LO));
    // TILE*16 groups of 8 elements
    for (int idx = tpart; idx < TILE * 16; idx += npart) {
        int row = idx >> 4;
        int k8  = (idx & 15) << 3;
        long gr = tile * TILE + row;
        float4 v0 = make_float4(0.f, 0.f, 0.f, 0.f), v1 = v0;
        if (gr < (long)V) {
            const float4* p = (const float4*)(H + (size_t)gr * D + k8);
            v0 = p[0];
            v1 = p[1];
        }
        float f[8] = {v0.x, v0.y, v0.z, v0.w, v1.x, v1.y, v1.z, v1.w};
        unsigned hi[4], lo[4];
#pragma unroll
        for (int p2 = 0; p2 < 4; ++p2) {
            __nv_bfloat16 ha = __float2bfloat16(f[2 * p2]);
            __nv_bfloat16 hb = __float2bfloat16(f[2 * p2 + 1]);
            __nv_bfloat16 la = __float2bfloat16(f[2 * p2] - __bfloat162float(ha));
            __nv_bfloat16 lb = __float2bfloat16(f[2 * p2 + 1] - __bfloat162float(hb));
            hi[p2] = pk(ha, hb);
            lo[p2] = pk(la, lb);
        }
        int off = row * AP + k8;
        *(uint4*)(dhi + off) = make_uint4(hi[0], hi[1], hi[2], hi[3]);
        *(uint4*)(dlo + off) = make_uint4(lo[0], lo[1], lo[2], lo[3]);
    }
}

__global__ __launch_bounds__(256, 1) void k1_tc(const float* __restrict__ H,
                                                const float* __restrict__ bp,
                                                const float* __restrict__ ws,
                                                int V, int nTiles) {
    extern __shared__ __align__(16) char smem[];
    int tid = threadIdx.x, wid = tid >> 5, lane = tid & 31;
    float* sb = (float*)(smem + SM_SB);
    float* sw = (float*)(smem + SM_SW);
    float* se = (float*)(smem + SM_SE);     // [2][64]

    if (tid < 128) { sb[tid] = bp[tid]; sw[tid] = ws[tid]; }

    // stage stationary B = W hi/lo (padded row-major, rows = hidden units)
    for (int idx = tid; idx < 128 * 16; idx += 256) {
        int row = idx >> 4;
        int k8  = (idx & 15) << 3;
        uint4 vh = *(const uint4*)(g_Whi + row * D + k8);
        uint4 vl = *(const uint4*)(g_Wlo + row * D + k8);
        int off = row * AP + k8;
        *(uint4*)((__nv_bfloat16*)(smem + SM_BHI) + off) = vh;
        *(uint4*)((__nv_bfloat16*)(smem + SM_BLO) + off) = vl;
    }

    int nt = 0;
    {
        int rem = nTiles - blockIdx.x;
        if (rem > 0) nt = (rem + (int)gridDim.x - 1) / (int)gridDim.x;
    }

    // prologue: all 256 threads stage tile 0 into buf 0
    if (nt > 0)
        stage_tile((char*)smem, H, (long)blockIdx.x, 0, V, tid, 256);
    __syncthreads();

    // consumer geometry (warps 0-3): 2x2, warp tile 32 rows x 64 cols
    int wm = wid >> 1, wn = wid & 1;
    int rb = wm * 32, cb = wn * 64;
    unsigned aoff = ((rb + (lane & 15)) * AP + ((lane >> 4) << 3)) * 2;
    unsigned boff =
        ((cb + (lane & 7) + ((lane >> 4) << 3)) * AP + (((lane >> 3) & 1) << 3)) * 2;
    unsigned bhi_s = su32(smem + SM_BHI), blo_s = su32(smem + SM_BLO);

    // epilogue constants
    float bv[16], wv[16];
    if (wid < 4) {
#pragma unroll
        for (int nt2 = 0; nt2 < 8; ++nt2)
#pragma unroll
            for (int par = 0; par < 2; ++par) {
                int col = cb + nt2 * 8 + (lane & 3) * 2 + par;
                bv[nt2 * 2 + par] = sb[col];
                wv[nt2 * 2 + par] = sw[col];
            }
    }

    for (int j = 0; j < nt; ++j) {
        int b = j & 1, bn = (j + 1) & 1;
        long tj = (long)blockIdx.x + (long)j * gridDim.x;

        if (wid >= 4) {
            if (j + 1 < nt) {
                long tj1 = (long)blockIdx.x + (long)(j + 1) * gridDim.x;
                stage_tile((char*)smem, H, tj1, bn, V, tid - 128, 128);
            }
        } else {
            unsigned ahi_s = su32(smem + (b ? SM_A1HI : SM_A0HI));
            unsigned alo_s = su32(smem + (b ? SM_A1LO : SM_A0LO));

            float acc[2][8][4];
#pragma unroll
            for (int a = 0; a < 2; a++)
#pragma unroll
                for (int q = 0; q < 8; q++)
#pragma unroll
                    for (int c = 0; c < 4; c++) acc[a][q][c] = 0.f;

#pragma unroll
            for (int pass = 0; pass < 3; ++pass) {
                unsigned abase = (pass == 2 ? alo_s : ahi_s) + aoff;
                unsigned bbase = (pass == 1 ? blo_s : bhi_s) + boff;
#pragma unroll
                for (int kk = 0; kk < 8; ++kk) {
                    unsigned a0, a1, a2, a3, a4, a5, a6, a7;
                    LDSM4(a0, a1, a2, a3, abase + kk * 32);
                    LDSM4(a4, a5, a6, a7, abase + kk * 32 + 16 * AP * 2);
                    unsigned bf[16];
#pragma unroll
                    for (int p = 0; p < 4; ++p)
                        LDSM4(bf[4 * p], bf[4 * p + 1], bf[4 * p + 2],
                              bf[4 * p + 3],
                              bbase + kk * 32 + p * (16 * AP * 2));
#pragma unroll
                    for (int q = 0; q < 8; ++q) {
                        int bi = (q >> 1) * 4 + ((q & 1) << 1);
                        MMA16816(acc[0][q], a0, a1, a2, a3, bf[bi], bf[bi + 1]);
                        MMA16816(acc[1][q], a4, a5, a6, a7, bf[bi], bf[bi + 1]);
                    }
                }
            }

            // epilogue: tanh + dot with w, reduce 4-lane groups
            float ps[4] = {0.f, 0.f, 0.f, 0.f};
#pragma unroll
            for (int mi = 0; mi < 2; ++mi)
#pragma unroll
                for (int q = 0; q < 8; ++q)
#pragma unroll
                    for (int e = 0; e < 4; ++e) {
                        float z = acc[mi][q][e] + bv[q * 2 + (e & 1)];
                        ps[mi * 2 + (e >> 1)] += tanh_fast(z) * wv[q * 2 + (e & 1)];
                    }
#pragma unroll
            for (int q = 0; q < 4; ++q) {
                ps[q] += __shfl_xor_sync(0xffffffffu, ps[q], 1);
                ps[q] += __shfl_xor_sync(0xffffffffu, ps[q], 2);
            }
            if ((lane & 3) == 0) {
#pragma unroll
                for (int q = 0; q < 4; ++q) {
                    int r = rb + (q >> 1) * 16 + (lane >> 2) + (q & 1) * 8;
                    se[wn * 64 + r] = ps[q];   // disjoint per (wm,wn): no atomics
                }
            }
            asm volatile("bar.sync 1, 128;" ::: "memory");
            if (tid < 64) {
                long grow = tj * TILE + tid;
                if (grow < (long)V) g_e[grow] = se[tid] + se[64 + tid];
            }
        }
        __syncthreads();
    }
}

// ---------------- K23: fused segment softmax + pooling ----------------
__global__ __launch_bounds__(128) void k23_pool(const float* __restrict__ H,
                                                float* __restrict__ out) {
    __shared__ float se[1024];
    __shared__ float red[128];
    int g = blockIdx.x, tid = threadIdx.x;
    int s = g_starts[g], t = g_starts[g + 1];
    int len = t - s;
    bool small = (len <= 1024);

    float m = -1e30f;
    if (small) {
        for (int i = tid; i < len; i += 128) {
            float e = g_e[s + i];
            se[i] = e;
            m = fmaxf(m, e);
        }
    } else {
        for (int i = tid; i < len; i += 128) m = fmaxf(m, g_e[s + i]);
    }
    red[tid] = m;
    __syncthreads();
#pragma unroll
    for (int o = 64; o > 0; o >>= 1) {
        if (tid < o) red[tid] = fmaxf(red[tid], red[tid + o]);
        __syncthreads();
    }
    m = red[0];
    __syncthreads();

    float sum = 0.f;
    if (small) {
        for (int i = tid; i < len; i += 128) {
            float a = __expf(se[i] - m);
            se[i] = a;
            sum += a;
        }
    } else {
        for (int i = tid; i < len; i += 128) sum += __expf(g_e[s + i] - m);
    }
    red[tid] = sum;
    __syncthreads();
#pragma unroll
    for (int o = 64; o > 0; o >>= 1) {
        if (tid < o) red[tid] += red[tid + o];
        __syncthreads();
    }
    float inv = 1.0f / fmaxf(red[0], 1e-12f);
    __syncthreads();

    int d = tid;
    float a0 = 0.f, a1 = 0.f, a2 = 0.f, a3 = 0.f;
    if (small) {
        int i = 0;
        for (; i + 3 < len; i += 4) {
            a0 += se[i]     * H[(size_t)(s + i)     * D + d];
            a1 += se[i + 1] * H[(size_t)(s + i + 1) * D + d];
            a2 += se[i + 2] * H[(size_t)(s + i + 2) * D + d];
            a3 += se[i + 3] * H[(size_t)(s + i + 3) * D + d];
        }
        for (; i < len; ++i) a0 += se[i] * H[(size_t)(s + i) * D + d];
    } else {
        for (int i = 0; i < len; ++i)
            a0 += __expf(g_e[s + i] - m) * H[(size_t)(s + i) * D + d];
    }
    out[(size_t)g * D + d] = (a0 + a1 + a2 + a3) * inv;
}

// ---------------- launch ----------------
extern "C" void kernel_launch(void* const* d_in, const int* in_sizes, int n_in,
                              void* d_out, int out_size) {
    const float* H  = (const float*)d_in[0];
    const void*  bt = d_in[1];
    const float* Wp = (const float*)d_in[2];
    const float* bp = (const float*)d_in[3];
    const float* ws = (const float*)d_in[4];
    float* out = (float*)d_out;

    int V = in_sizes[1];
    int G = out_size / D;
    if (G > MAXG) G = MAXG;
    int nTiles = (V + TILE - 1) / TILE;

    cudaFuncSetAttribute(k1_tc, cudaFuncAttributeMaxDynamicSharedMemorySize,
                         SMEM1_TOTAL);

    k_prep_w<<<(HS * D + 255) / 256, 256>>>(Wp);
    k_bounds<<<(V + 255) / 256, 256>>>(bt, V, G);
    k1_tc<<<NSM, 256, SMEM1_TOTAL>>>(H, bp, ws, V, nTiles);
    k23_pool<<<G, 128>>>(H, out);
}

// round 4
// speedup vs baseline: 1.3014x; 1.0620x over previous
#include <cuda_runtime.h>
#include <cuda_bf16.h>
#include <cstdint>

#define D    128
#define HS   128
#define MAXV 1000064
#define MAXG 16384
#define AP   136      // padded smem row pitch in bf16 elems
#define TILE 128      // rows per tile
#define NSM  148

// ---------------- device scratch ----------------
__device__ float g_e[MAXV];
__device__ int   g_starts[MAXG + 1];
__device__ __align__(16) __nv_bfloat16 g_Whi[HS * D];
__device__ __align__(16) __nv_bfloat16 g_Wlo[HS * D];

// ---------------- smem layout (bytes) ----------------
#define SM_SB    0                       // 128 f32 bias
#define SM_SW    512                     // 128 f32 w_score
#define SM_SE    1024                    // 2 x 128 f32 = 1024
#define SM_BHI   2048                    // 128 x AP bf16 = 34816
#define SM_BLO   (SM_BHI + 34816)        // 36864
#define SM_A0HI  (SM_BLO + 34816)        // 71680
#define SM_A0LO  (SM_A0HI + 34816)       // 106496
#define SM_A1HI  (SM_A0LO + 34816)       // 141312
#define SM_A1LO  (SM_A1HI + 34816)       // 176128
#define SMEM1_TOTAL (SM_A1LO + 34816)    // 210944

// ---------------- helpers ----------------
__device__ __forceinline__ unsigned su32(const void* p) {
    return (unsigned)__cvta_generic_to_shared(p);
}
__device__ __forceinline__ unsigned pk(__nv_bfloat16 a, __nv_bfloat16 b) {
    unsigned short ua = *(unsigned short*)&a, ub = *(unsigned short*)&b;
    return (unsigned)ua | ((unsigned)ub << 16);
}
__device__ __forceinline__ float tanh_approx(float x) {
    float y;
    asm("tanh.approx.f32 %0, %1;" : "=f"(y) : "f"(x));
    return y;
}

#define LDSM4(r0, r1, r2, r3, addr)                                          \
    asm volatile("ldmatrix.sync.aligned.m8n8.x4.shared.b16 {%0,%1,%2,%3}, [%4];" \
                 : "=r"(r0), "=r"(r1), "=r"(r2), "=r"(r3) : "r"(addr))

#define MMA16816(c, a0, a1, a2, a3, b0, b1)                                  \
    asm volatile(                                                            \
        "mma.sync.aligned.m16n8k16.row.col.f32.bf16.bf16.f32 "               \
        "{%0,%1,%2,%3},{%4,%5,%6,%7},{%8,%9},{%0,%1,%2,%3};"                 \
        : "+f"(c[0]), "+f"(c[1]), "+f"(c[2]), "+f"(c[3])                     \
        : "r"(a0), "r"(a1), "r"(a2), "r"(a3), "r"(b0), "r"(b1))

// ---------------- small kernels ----------------
__global__ void k_prep_w(const float* __restrict__ W) {
    int i = blockIdx.x * 256 + threadIdx.x;
    if (i < HS * D) {
        float x = W[i];
        __nv_bfloat16 h = __float2bfloat16(x);
        g_Whi[i] = h;
        g_Wlo[i] = __float2bfloat16(x - __bfloat162float(h));
    }
}

__global__ void k_bounds(const void* __restrict__ batch_raw, int V, int G) {
    int i = blockIdx.x * 256 + threadIdx.x;
    if (i >= V) return;
    bool is64 =
        (((const unsigned long long*)batch_raw)[V / 2 - 1] < (1ULL << 31));
    auto bat = [&](int j) -> int {
        return is64 ? (int)((const long long*)batch_raw)[j]
                    : ((const int*)batch_raw)[j];
    };
    int cur = bat(i);
    int prev = (i == 0) ? -1 : bat(i - 1);
    for (int g = prev + 1; g <= cur && g <= G; ++g) g_starts[g] = i;
    if (i == V - 1)
        for (int g = cur + 1; g <= G; ++g) g_starts[g] = V;
}

// ---------------- K1 staging: TILE x 128 fp32 -> bf16 hi/lo ----------------
__device__ __forceinline__ void stage_tile(char* smem, const float* __restrict__ H,
                                           long tile, int buf, int V,
                                           int tpart, int npart) {
    __nv_bfloat16* dhi = (__nv_bfloat16*)(smem + (buf ? SM_A1HI : SM_A0HI));
    __nv_bfloat16* dlo = (__nv_bfloat16*)(smem + (buf ? SM_A1LO : SM_A0LO));
    for (int idx = tpart; idx < TILE * 16; idx += npart) {
        int row = idx >> 4;
        int k8  = (idx & 15) << 3;
        long gr = tile * TILE + row;
        float4 v0 = make_float4(0.f, 0.f, 0.f, 0.f), v1 = v0;
        if (gr < (long)V) {
            const float4* p = (const float4*)(H + (size_t)gr * D + k8);
            v0 = p[0];
            v1 = p[1];
        }
        float f[8] = {v0.x, v0.y, v0.z, v0.w, v1.x, v1.y, v1.z, v1.w};
        unsigned hi[4], lo[4];
#pragma unroll
        for (int p2 = 0; p2 < 4; ++p2) {
            __nv_bfloat16 ha = __float2bfloat16(f[2 * p2]);
            __nv_bfloat16 hb = __float2bfloat16(f[2 * p2 + 1]);
            __nv_bfloat16 la = __float2bfloat16(f[2 * p2] - __bfloat162float(ha));
            __nv_bfloat16 lb = __float2bfloat16(f[2 * p2 + 1] - __bfloat162float(hb));
            hi[p2] = pk(ha, hb);
            lo[p2] = pk(la, lb);
        }
        int off = row * AP + k8;
        *(uint4*)(dhi + off) = make_uint4(hi[0], hi[1], hi[2], hi[3]);
        *(uint4*)(dlo + off) = make_uint4(lo[0], lo[1], lo[2], lo[3]);
    }
}

// ---------------- K1: persistent split-bf16 HMMA, 64x64 warp tiles --------
__global__ __launch_bounds__(256, 1) void k1_tc(const float* __restrict__ H,
                                                const float* __restrict__ bp,
                                                const float* __restrict__ ws,
                                                int V, int nTiles) {
    extern __shared__ __align__(16) char smem[];
    int tid = threadIdx.x, wid = tid >> 5, lane = tid & 31;
    float* sb = (float*)(smem + SM_SB);
    float* sw = (float*)(smem + SM_SW);
    float* se = (float*)(smem + SM_SE);   // [2][128]

    if (tid < 128) { sb[tid] = bp[tid]; sw[tid] = ws[tid]; }

    // stage stationary B = W hi/lo
    for (int idx = tid; idx < 128 * 16; idx += 256) {
        int row = idx >> 4;
        int k8  = (idx & 15) << 3;
        uint4 vh = *(const uint4*)(g_Whi + row * D + k8);
        uint4 vl = *(const uint4*)(g_Wlo + row * D + k8);
        int off = row * AP + k8;
        *(uint4*)((__nv_bfloat16*)(smem + SM_BHI) + off) = vh;
        *(uint4*)((__nv_bfloat16*)(smem + SM_BLO) + off) = vl;
    }

    int nt = 0;
    {
        int rem = nTiles - blockIdx.x;
        if (rem > 0) nt = (rem + (int)gridDim.x - 1) / (int)gridDim.x;
    }

    if (nt > 0)
        stage_tile((char*)smem, H, (long)blockIdx.x, 0, V, tid, 256);
    __syncthreads();

    // consumer geometry (warps 0-3): 2(M) x 2(N), warp tile 64 x 64
    int wm = wid >> 1, wn = wid & 1;
    int rb = wm * 64, cb = wn * 64;
    unsigned aoff = ((rb + (lane & 15)) * AP + ((lane >> 4) << 3)) * 2;
    unsigned boff =
        ((cb + (lane & 7) + ((lane >> 4) << 3)) * AP + (((lane >> 3) & 1) << 3)) * 2;
    unsigned bhi_s = su32(smem + SM_BHI) + boff;
    unsigned blo_s = su32(smem + SM_BLO) + boff;

    for (int j = 0; j < nt; ++j) {
        int b = j & 1, bn = (j + 1) & 1;
        long tj = (long)blockIdx.x + (long)j * gridDim.x;

        if (wid >= 4) {
            if (j + 1 < nt) {
                long tj1 = (long)blockIdx.x + (long)(j + 1) * gridDim.x;
                stage_tile((char*)smem, H, tj1, bn, V, tid - 128, 128);
            }
        } else {
            unsigned ahi_s = su32(smem + (b ? SM_A1HI : SM_A0HI)) + aoff;
            unsigned alo_s = su32(smem + (b ? SM_A1LO : SM_A0LO)) + aoff;

            float acc[4][8][4];
#pragma unroll
            for (int s = 0; s < 4; s++)
#pragma unroll
                for (int q = 0; q < 8; q++)
#pragma unroll
                    for (int c = 0; c < 4; c++) acc[s][q][c] = 0.f;

#pragma unroll
            for (int kk = 0; kk < 8; ++kk) {
                unsigned ah[4][4], bh[16];
                // A-hi fragments (4 m16 subtiles)
#pragma unroll
                for (int s = 0; s < 4; ++s)
                    LDSM4(ah[s][0], ah[s][1], ah[s][2], ah[s][3],
                          ahi_s + kk * 32 + s * (16 * AP * 2));
                // B-hi fragments (4 n16 groups)
#pragma unroll
                for (int p = 0; p < 4; ++p)
                    LDSM4(bh[4 * p], bh[4 * p + 1], bh[4 * p + 2], bh[4 * p + 3],
                          bhi_s + kk * 32 + p * (16 * AP * 2));
                // pass 0: Ahi * Bhi
#pragma unroll
                for (int s = 0; s < 4; ++s)
#pragma unroll
                    for (int q = 0; q < 8; ++q) {
                        int bi = (q >> 1) * 4 + ((q & 1) << 1);
                        MMA16816(acc[s][q], ah[s][0], ah[s][1], ah[s][2],
                                 ah[s][3], bh[bi], bh[bi + 1]);
                    }
                // pass 1: Ahi * Blo
                unsigned bl[16];
#pragma unroll
                for (int p = 0; p < 4; ++p)
                    LDSM4(bl[4 * p], bl[4 * p + 1], bl[4 * p + 2], bl[4 * p + 3],
                          blo_s + kk * 32 + p * (16 * AP * 2));
#pragma unroll
                for (int s = 0; s < 4; ++s)
#pragma unroll
                    for (int q = 0; q < 8; ++q) {
                        int bi = (q >> 1) * 4 + ((q & 1) << 1);
                        MMA16816(acc[s][q], ah[s][0], ah[s][1], ah[s][2],
                                 ah[s][3], bl[bi], bl[bi + 1]);
                    }
                // pass 2: Alo * Bhi
                unsigned al[4][4];
#pragma unroll
                for (int s = 0; s < 4; ++s)
                    LDSM4(al[s][0], al[s][1], al[s][2], al[s][3],
                          alo_s + kk * 32 + s * (16 * AP * 2));
#pragma unroll
                for (int s = 0; s < 4; ++s)
#pragma unroll
                    for (int q = 0; q < 8; ++q) {
                        int bi = (q >> 1) * 4 + ((q & 1) << 1);
                        MMA16816(acc[s][q], al[s][0], al[s][1], al[s][2],
                                 al[s][3], bh[bi], bh[bi + 1]);
                    }
            }

            // epilogue: tanh + dot with w
            float bv[16], wv[16];
#pragma unroll
            for (int q = 0; q < 8; ++q)
#pragma unroll
                for (int par = 0; par < 2; ++par) {
                    int col = cb + q * 8 + (lane & 3) * 2 + par;
                    bv[q * 2 + par] = sb[col];
                    wv[q * 2 + par] = sw[col];
                }
            float ps[8];
#pragma unroll
            for (int q = 0; q < 8; ++q) ps[q] = 0.f;
#pragma unroll
            for (int s = 0; s < 4; ++s)
#pragma unroll
                for (int q = 0; q < 8; ++q)
#pragma unroll
                    for (int e = 0; e < 4; ++e) {
                        float z = acc[s][q][e] + bv[q * 2 + (e & 1)];
                        ps[s * 2 + (e >> 1)] += tanh_approx(z) * wv[q * 2 + (e & 1)];
                    }
#pragma unroll
            for (int q = 0; q < 8; ++q) {
                ps[q] += __shfl_xor_sync(0xffffffffu, ps[q], 1);
                ps[q] += __shfl_xor_sync(0xffffffffu, ps[q], 2);
            }
            if ((lane & 3) == 0) {
#pragma unroll
                for (int q = 0; q < 8; ++q) {
                    int r = rb + (q >> 1) * 16 + (lane >> 2) + (q & 1) * 8;
                    se[wn * 128 + r] = ps[q];   // disjoint per (wm,wn)
                }
            }
            asm volatile("bar.sync 1, 128;" ::: "memory");
            if (tid < 128) {
                long grow = tj * TILE + tid;
                if (grow < (long)V) g_e[grow] = se[tid] + se[128 + tid];
            }
        }
        __syncthreads();
    }
}

// ---------------- K23: fused segment softmax + pooling ----------------
__global__ __launch_bounds__(128) void k23_pool(const float* __restrict__ H,
                                                float* __restrict__ out) {
    __shared__ float se[1024];
    __shared__ float red[128];
    int g = blockIdx.x, tid = threadIdx.x;
    int s = g_starts[g], t = g_starts[g + 1];
    int len = t - s;
    bool small = (len <= 1024);

    float m = -1e30f;
    if (small) {
        for (int i = tid; i < len; i += 128) {
            float e = g_e[s + i];
            se[i] = e;
            m = fmaxf(m, e);
        }
    } else {
        for (int i = tid; i < len; i += 128) m = fmaxf(m, g_e[s + i]);
    }
    red[tid] = m;
    __syncthreads();
#pragma unroll
    for (int o = 64; o > 0; o >>= 1) {
        if (tid < o) red[tid] = fmaxf(red[tid], red[tid + o]);
        __syncthreads();
    }
    m = red[0];
    __syncthreads();

    float sum = 0.f;
    if (small) {
        for (int i = tid; i < len; i += 128) {
            float a = __expf(se[i] - m);
            se[i] = a;
            sum += a;
        }
    } else {
        for (int i = tid; i < len; i += 128) sum += __expf(g_e[s + i] - m);
    }
    red[tid] = sum;
    __syncthreads();
#pragma unroll
    for (int o = 64; o > 0; o >>= 1) {
        if (tid < o) red[tid] += red[tid + o];
        __syncthreads();
    }
    float inv = 1.0f / fmaxf(red[0], 1e-12f);
    __syncthreads();

    int d = tid;
    float a0 = 0.f, a1 = 0.f, a2 = 0.f, a3 = 0.f;
    if (small) {
        int i = 0;
        for (; i + 3 < len; i += 4) {
            a0 += se[i]     * H[(size_t)(s + i)     * D + d];
            a1 += se[i + 1] * H[(size_t)(s + i + 1) * D + d];
            a2 += se[i + 2] * H[(size_t)(s + i + 2) * D + d];
            a3 += se[i + 3] * H[(size_t)(s + i + 3) * D + d];
        }
        for (; i < len; ++i) a0 += se[i] * H[(size_t)(s + i) * D + d];
    } else {
        for (int i = 0; i < len; ++i)
            a0 += __expf(g_e[s + i] - m) * H[(size_t)(s + i) * D + d];
    }
    out[(size_t)g * D + d] = (a0 + a1 + a2 + a3) * inv;
}

// ---------------- launch ----------------
extern "C" void kernel_launch(void* const* d_in, const int* in_sizes, int n_in,
                              void* d_out, int out_size) {
    const float* H  = (const float*)d_in[0];
    const void*  bt = d_in[1];
    const float* Wp = (const float*)d_in[2];
    const float* bp = (const float*)d_in[3];
    const float* ws = (const float*)d_in[4];
    float* out = (float*)d_out;

    int V = in_sizes[1];
    int G = out_size / D;
    if (G > MAXG) G = MAXG;
    int nTiles = (V + TILE - 1) / TILE;

    cudaFuncSetAttribute(k1_tc, cudaFuncAttributeMaxDynamicSharedMemorySize,
                         SMEM1_TOTAL);

    k_prep_w<<<(HS * D + 255) / 256, 256>>>(Wp);
    k_bounds<<<(V + 255) / 256, 256>>>(bt, V, G);
    k1_tc<<<NSM, 256, SMEM1_TOTAL>>>(H, bp, ws, V, nTiles);
    k23_pool<<<G, 128>>>(H, out);
}